// round 12
// baseline (speedup 1.0000x reference)
#include <cuda_runtime.h>
#include <cuda_fp16.h>
#include <math_constants.h>
#include <cstdint>

// ---------------------------------------------------------------------------
// RPE_Attention: x[64,197,768] -> qkv -> per-head attention (+rel pos bias) ->
// proj.
// GEMMs: fp16 mma.sync 3-term Markidis split, 128x128 tile, 8 warps (2x4),
//        warp tile 64x32, BK=16, 4-stage cp.async pipeline + REGISTER-level
//        B-fragment double buffering (ldsm for it+1 overlapped with HMMA of it).
// Attention: tensorized mma.sync + direct hi/lo split output (R10, proven).
// ---------------------------------------------------------------------------

#define BATCH 64
#define NQ    197
#define CDIM  768
#define NH    12
#define HD    64
#define NP    196
#define MTOT  (BATCH * NQ)          // 12608

__device__ float   g_qkv[(size_t)MTOT * 3 * CDIM];
__device__ __half2 g_xhi[(size_t)MTOT * CDIM / 2];
__device__ __half2 g_xlo[(size_t)MTOT * CDIM / 2];
__device__ __half2 g_whi[(size_t)3 * CDIM * CDIM / 2];
__device__ __half2 g_wlo[(size_t)3 * CDIM * CDIM / 2];
__device__ __half2 g_phi[(size_t)CDIM * CDIM / 2];
__device__ __half2 g_plo[(size_t)CDIM * CDIM / 2];
__device__ __half2 g_ahi[(size_t)MTOT * CDIM / 2];
__device__ __half2 g_alo[(size_t)MTOT * CDIM / 2];

// ===========================================================================
// common helpers
// ===========================================================================
__device__ __forceinline__ unsigned smem_u32(const void* p) {
    return (unsigned)__cvta_generic_to_shared(p);
}
__device__ __forceinline__ void cp_async16(unsigned dst, const void* src, bool pred) {
    int sz = pred ? 16 : 0;
    asm volatile("cp.async.cg.shared.global [%0], [%1], 16, %2;\n"
                 :: "r"(dst), "l"(src), "r"(sz));
}
__device__ __forceinline__ void cp_commit() { asm volatile("cp.async.commit_group;\n"); }
__device__ __forceinline__ void cp_wait1()  { asm volatile("cp.async.wait_group 1;\n"); }
__device__ __forceinline__ void cp_wait2()  { asm volatile("cp.async.wait_group 2;\n"); }

__device__ __forceinline__ void ldsm_x4(uint32_t* r, unsigned a) {
    asm volatile("ldmatrix.sync.aligned.m8n8.x4.shared.b16 {%0,%1,%2,%3}, [%4];"
                 : "=r"(r[0]), "=r"(r[1]), "=r"(r[2]), "=r"(r[3]) : "r"(a));
}
__device__ __forceinline__ void mma_f16(float* d, const uint32_t* a, const uint32_t* b) {
    asm volatile(
        "mma.sync.aligned.m16n8k16.row.col.f32.f16.f16.f32 "
        "{%0,%1,%2,%3}, {%4,%5,%6,%7}, {%8,%9}, {%0,%1,%2,%3};"
        : "+f"(d[0]), "+f"(d[1]), "+f"(d[2]), "+f"(d[3])
        : "r"(a[0]), "r"(a[1]), "r"(a[2]), "r"(a[3]), "r"(b[0]), "r"(b[1]));
}

// ===========================================================================
// split: fp32 -> (hi, lo) fp16 planes.
// ===========================================================================
__global__ void split_h(const float4* __restrict__ src, __half2* __restrict__ hi,
                        __half2* __restrict__ lo, int n4)
{
    int i = blockIdx.x * blockDim.x + threadIdx.x;
    if (i >= n4) return;
    float4 v = src[i];
    __half2 h0 = __floats2half2_rn(v.x, v.y);
    __half2 h1 = __floats2half2_rn(v.z, v.w);
    float2 f0 = __half22float2(h0);
    float2 f1 = __half22float2(h1);
    __half2 l0 = __floats2half2_rn(v.x - f0.x, v.y - f0.y);
    __half2 l1 = __floats2half2_rn(v.z - f1.x, v.w - f1.y);
    hi[2 * i]     = h0;
    hi[2 * i + 1] = h1;
    lo[2 * i]     = l0;
    lo[2 * i + 1] = l1;
}

// ===========================================================================
// fp16-split GEMM (NT), v4: BM=BN=128, BK=16, 256 thr = 8 warps (2x4),
// warp tile 64x32.  4-stage cp.async pipeline + register B-frag double buffer.
// Stage layout (halfs, stride 24): Ahi[128x24] Alo Bhi[128x24] Blo
// ===========================================================================
#define S24     24
#define PL3     (128 * S24)            // 3072 halfs per plane
#define STG_H   (4 * PL3)              // 12288 halfs per stage
#define STG_B   (STG_H * 2)            // 24576 bytes
#define G4SMEM  (4 * STG_B)            // 98304 bytes

__global__ __launch_bounds__(256) void gemm_f16s4(
    const __half* __restrict__ Ahi, const __half* __restrict__ Alo,
    const __half* __restrict__ Bhi, const __half* __restrict__ Blo,
    const float* __restrict__ bias, float* __restrict__ C,
    int M, int N, int K)
{
    extern __shared__ __half smg[];

    const int tid  = threadIdx.x;
    const int lane = tid & 31;
    const int wid  = tid >> 5;
    const int wm   = wid & 1;          // 64-row band
    const int wn   = wid >> 1;         // 32-col band (0..3)
    const int bm   = blockIdx.y * 128;
    const int bn   = blockIdx.x * 128;
    const unsigned sbase = smem_u32(smg);

    // loader: thread -> one row-half (16B) per plane
    const int lrow = tid >> 1;
    const int lh   = tid & 1;
    const bool aok = (bm + lrow) < M;
    const __half* gAh = Ahi + (size_t)(aok ? bm + lrow : 0) * K + lh * 8;
    const __half* gAl = Alo + (size_t)(aok ? bm + lrow : 0) * K + lh * 8;
    const __half* gBh = Bhi + (size_t)(bn + lrow) * K + lh * 8;
    const __half* gBl = Blo + (size_t)(bn + lrow) * K + lh * 8;
    const unsigned sA = sbase + (unsigned)(lrow * S24 + lh * 8) * 2u;
    const unsigned sB = sA + (unsigned)(2 * PL3) * 2u;

    const int nIter = K / 16;          // 48

    auto load_stage = [&](int it3) {
        const unsigned off = (unsigned)(it3 & 3) * STG_B;
        const int k0 = it3 * 16;
        cp_async16(sA + off,           gAh + k0, aok);
        cp_async16(sA + off + PL3 * 2, gAl + k0, aok);
        cp_async16(sB + off,           gBh + k0, true);
        cp_async16(sB + off + PL3 * 2, gBl + k0, true);
    };

    float acc[4][4][4];
#pragma unroll
    for (int i = 0; i < 4; i++)
#pragma unroll
        for (int j = 0; j < 4; j++)
#pragma unroll
            for (int r = 0; r < 4; r++) acc[i][j][r] = 0.f;

    // fragment addresses
    const int arow = wm * 64 + (lane & 15);
    const int acol = (lane >> 4) * 8;
    const int q    = lane >> 3;                         // ldsm_x4 group
    const int brow = wn * 32 + (q >> 1) * 8 + (lane & 7);
    const int bcol = (q & 1) * 8;

    // B fragment double buffer: [buf][pair][4 regs] (each x4 = 2 n-tiles)
    uint32_t bhf[2][2][4], blf[2][2][4];

    // prologue: stages 0,1,2 in flight; prime B frags for it=0
    load_stage(0); cp_commit();
    load_stage(1); cp_commit();
    load_stage(2); cp_commit();
    cp_wait2();                 // group 0 done -> stage 0 resident
    __syncthreads();
    {
        const __half* sb0 = smg + 2 * PL3;
        const __half* sb1 = smg + 3 * PL3;
#pragma unroll
        for (int p = 0; p < 2; p++) {
            ldsm_x4(bhf[0][p], smem_u32(sb0 + (brow + p * 16) * S24 + bcol));
            ldsm_x4(blf[0][p], smem_u32(sb1 + (brow + p * 16) * S24 + bcol));
        }
    }

#pragma unroll 2
    for (int it = 0; it < nIter; it++) {
        const int cur = it & 1;
        const int nxt = cur ^ 1;

        cp_wait1();            // stages it, it+1 resident (pending: it+2)
        __syncthreads();       // visibility + all warps past reads of stage it-1

        if (it + 3 < nIter) load_stage(it + 3);
        cp_commit();           // unconditional: keep group count stable

        // prefetch B frags for it+1 (stage it+1 resident; consumed next iter)
        if (it + 1 < nIter) {
            const __half* stn = smg + ((it + 1) & 3) * STG_H;
            const __half* sbn0 = stn + 2 * PL3;
            const __half* sbn1 = stn + 3 * PL3;
#pragma unroll
            for (int p = 0; p < 2; p++) {
                ldsm_x4(bhf[nxt][p], smem_u32(sbn0 + (brow + p * 16) * S24 + bcol));
                ldsm_x4(blf[nxt][p], smem_u32(sbn1 + (brow + p * 16) * S24 + bcol));
            }
        }

        // HMMA block for iter it (A frags just-in-time per mt)
        const __half* st  = smg + (it & 3) * STG_H;
        const __half* sa0 = st;
        const __half* sa1 = st + PL3;
#pragma unroll
        for (int mt = 0; mt < 4; mt++) {
            uint32_t ah[4], al[4];
            ldsm_x4(ah, smem_u32(sa0 + (arow + mt * 16) * S24 + acol));
            ldsm_x4(al, smem_u32(sa1 + (arow + mt * 16) * S24 + acol));
#pragma unroll
            for (int nt = 0; nt < 4; nt++)
                mma_f16(acc[mt][nt], ah, &bhf[cur][nt >> 1][(nt & 1) * 2]);
#pragma unroll
            for (int nt = 0; nt < 4; nt++)
                mma_f16(acc[mt][nt], al, &bhf[cur][nt >> 1][(nt & 1) * 2]);
#pragma unroll
            for (int nt = 0; nt < 4; nt++)
                mma_f16(acc[mt][nt], ah, &blf[cur][nt >> 1][(nt & 1) * 2]);
        }
    }

    // epilogue
    const int g = lane >> 2;
    const int t = lane & 3;
#pragma unroll
    for (int mt = 0; mt < 4; mt++) {
        const int r0 = bm + wm * 64 + mt * 16 + g;
#pragma unroll
        for (int nt = 0; nt < 4; nt++) {
            const int col = bn + wn * 32 + nt * 8 + 2 * t;
            const float bv0 = bias ? bias[col]     : 0.f;
            const float bv1 = bias ? bias[col + 1] : 0.f;
            if (r0 < M) {
                float2 v = make_float2(acc[mt][nt][0] + bv0, acc[mt][nt][1] + bv1);
                *(float2*)&C[(size_t)r0 * N + col] = v;
            }
            if (r0 + 8 < M) {
                float2 v = make_float2(acc[mt][nt][2] + bv0, acc[mt][nt][3] + bv1);
                *(float2*)&C[(size_t)(r0 + 8) * N + col] = v;
            }
        }
    }
}

// ===========================================================================
// Tensorized attention (R10, unchanged): direct hi/lo split output.
// ===========================================================================
#define NPAD   208
#define QKS    72
#define VTS    232
#define QH_OFF 0
#define QL_OFF (NPAD * QKS)
#define KH_OFF (2 * NPAD * QKS)
#define KL_OFF (3 * NPAD * QKS)
#define VTH_OFF (4 * NPAD * QKS)
#define VTL_OFF (VTH_OFF + HD * VTS)
#define ATM_HALFS (VTL_OFF + HD * VTS)
#define ATM_SMEM  (ATM_HALFS * 2 + 736 * 4)

__device__ __forceinline__ void pack2(float x, float y, uint32_t& hi, uint32_t& lo) {
    __half2 h = __floats2half2_rn(x, y);
    float2 f = __half22float2(h);
    __half2 l = __floats2half2_rn(x - f.x, y - f.y);
    hi = *reinterpret_cast<uint32_t*>(&h);
    lo = *reinterpret_cast<uint32_t*>(&l);
}

__global__ __launch_bounds__(256, 1) void attn_mma(
    const float* __restrict__ qkv, const float* __restrict__ rpb_table,
    const int* __restrict__ rel_idx,
    uint32_t* __restrict__ ohi, uint32_t* __restrict__ olo)
{
    extern __shared__ __align__(16) __half sma[];
    __half* QH  = sma + QH_OFF;
    __half* QL  = sma + QL_OFF;
    __half* KH  = sma + KH_OFF;
    __half* KL  = sma + KL_OFF;
    __half* VTH = sma + VTH_OFF;
    __half* VTL = sma + VTL_OFF;
    float*  bias_s = (float*)(sma + ATM_HALFS);

    const int tid  = threadIdx.x;
    const int lane = tid & 31;
    const int wid  = tid >> 5;
    const int b = blockIdx.x / NH;
    const int h = blockIdx.x % NH;

    const float* base0 = qkv + (size_t)b * NQ * (3 * CDIM) + h * HD;
    for (int i = tid; i < NPAD * HD; i += 256) {
        const int n = i >> 6, d = i & 63;
        float qv = 0.f, kv = 0.f, vv = 0.f;
        if (n < NQ) {
            const float* p = base0 + (size_t)n * (3 * CDIM) + d;
            qv = p[0] * 0.125f;
            kv = p[CDIM];
            vv = p[2 * CDIM];
        }
        __half qh_ = __float2half_rn(qv);
        QH[n * QKS + d] = qh_;
        QL[n * QKS + d] = __float2half_rn(qv - __half2float(qh_));
        __half kh_ = __float2half_rn(kv);
        KH[n * QKS + d] = kh_;
        KL[n * QKS + d] = __float2half_rn(kv - __half2float(kh_));
        __half vh_ = __float2half_rn(vv);
        VTH[d * VTS + n] = vh_;
        VTL[d * VTS + n] = __float2half_rn(vv - __half2float(vh_));
    }
    for (int i = tid; i < 729; i += 256) bias_s[i] = rpb_table[i * NH + h];
    __syncthreads();

    const int g = lane >> 2;
    const int t = lane & 3;
    const int idx = lane >> 3;

    for (int mt = wid; mt < 13; mt += 8) {
        const int q0 = mt * 16;

        uint32_t qfh[4][4], qfl[4][4];
        {
            const int row = q0 + (lane & 15);
            const int col = (lane >> 4) * 8;
#pragma unroll
            for (int kt = 0; kt < 4; kt++) {
                ldsm_x4(qfh[kt], smem_u32(QH + row * QKS + kt * 16 + col));
                ldsm_x4(qfl[kt], smem_u32(QL + row * QKS + kt * 16 + col));
            }
        }

        float sc[26][4];
#pragma unroll
        for (int nt = 0; nt < 26; nt++)
#pragma unroll
            for (int e = 0; e < 4; e++) sc[nt][e] = 0.f;

#pragma unroll
        for (int ntp = 0; ntp < 13; ntp++) {
            const int row = ntp * 16 + (idx >> 1) * 8 + (lane & 7);
            const int col = (idx & 1) * 8;
            uint32_t kf[4][4], lf[4][4];
#pragma unroll
            for (int kt = 0; kt < 4; kt++) {
                ldsm_x4(kf[kt], smem_u32(KH + row * QKS + kt * 16 + col));
                ldsm_x4(lf[kt], smem_u32(KL + row * QKS + kt * 16 + col));
            }
#pragma unroll
            for (int kt = 0; kt < 4; kt++) {
                mma_f16(sc[2 * ntp],     qfh[kt], &kf[kt][0]);
                mma_f16(sc[2 * ntp + 1], qfh[kt], &kf[kt][2]);
                mma_f16(sc[2 * ntp],     qfl[kt], &kf[kt][0]);
                mma_f16(sc[2 * ntp + 1], qfl[kt], &kf[kt][2]);
                mma_f16(sc[2 * ntp],     qfh[kt], &lf[kt][0]);
                mma_f16(sc[2 * ntp + 1], qfh[kt], &lf[kt][2]);
            }
        }

        const int qa = q0 + g;
        const int qb = q0 + g + 8;
        const bool va = qa < NQ;
        const bool vb = qb < NQ;
#pragma unroll
        for (int nt = 0; nt < 26; nt++) {
            const int j0 = nt * 8 + 2 * t;
            const int j1 = j0 + 1;
            {
                float s = sc[nt][0];
                if (!va) s = 0.f;
                else if (j0 >= NQ) s = -CUDART_INF_F;
                else if (qa > 0 && j0 > 0)
                    s += bias_s[__ldg(rel_idx + (qa - 1) * NP + (j0 - 1))];
                sc[nt][0] = s;
            }
            {
                float s = sc[nt][1];
                if (!va) s = 0.f;
                else if (j1 >= NQ) s = -CUDART_INF_F;
                else if (qa > 0)
                    s += bias_s[__ldg(rel_idx + (qa - 1) * NP + (j1 - 1))];
                sc[nt][1] = s;
            }
            {
                float s = sc[nt][2];
                if (!vb) s = 0.f;
                else if (j0 >= NQ) s = -CUDART_INF_F;
                else if (qb > 0 && j0 > 0)
                    s += bias_s[__ldg(rel_idx + (qb - 1) * NP + (j0 - 1))];
                sc[nt][2] = s;
            }
            {
                float s = sc[nt][3];
                if (!vb) s = 0.f;
                else if (j1 >= NQ) s = -CUDART_INF_F;
                else if (qb > 0)
                    s += bias_s[__ldg(rel_idx + (qb - 1) * NP + (j1 - 1))];
                sc[nt][3] = s;
            }
        }

        float mA = -CUDART_INF_F, mB = -CUDART_INF_F;
#pragma unroll
        for (int nt = 0; nt < 26; nt++) {
            mA = fmaxf(mA, fmaxf(sc[nt][0], sc[nt][1]));
            mB = fmaxf(mB, fmaxf(sc[nt][2], sc[nt][3]));
        }
        mA = fmaxf(mA, __shfl_xor_sync(0xffffffffu, mA, 1));
        mA = fmaxf(mA, __shfl_xor_sync(0xffffffffu, mA, 2));
        mB = fmaxf(mB, __shfl_xor_sync(0xffffffffu, mB, 1));
        mB = fmaxf(mB, __shfl_xor_sync(0xffffffffu, mB, 2));

        float eA = 0.f, eB = 0.f;
#pragma unroll
        for (int nt = 0; nt < 26; nt++) {
            sc[nt][0] = __expf(sc[nt][0] - mA);
            sc[nt][1] = __expf(sc[nt][1] - mA);
            sc[nt][2] = __expf(sc[nt][2] - mB);
            sc[nt][3] = __expf(sc[nt][3] - mB);
            eA += sc[nt][0] + sc[nt][1];
            eB += sc[nt][2] + sc[nt][3];
        }
        eA += __shfl_xor_sync(0xffffffffu, eA, 1);
        eA += __shfl_xor_sync(0xffffffffu, eA, 2);
        eB += __shfl_xor_sync(0xffffffffu, eB, 1);
        eB += __shfl_xor_sync(0xffffffffu, eB, 2);
        const float invA = 1.f / eA;
        const float invB = 1.f / eB;

        uint32_t ph[13][4], pl[13][4];
#pragma unroll
        for (int kt = 0; kt < 13; kt++) {
            pack2(sc[2 * kt][0] * invA,     sc[2 * kt][1] * invA,     ph[kt][0], pl[kt][0]);
            pack2(sc[2 * kt][2] * invB,     sc[2 * kt][3] * invB,     ph[kt][1], pl[kt][1]);
            pack2(sc[2 * kt + 1][0] * invA, sc[2 * kt + 1][1] * invA, ph[kt][2], pl[kt][2]);
            pack2(sc[2 * kt + 1][2] * invB, sc[2 * kt + 1][3] * invB, ph[kt][3], pl[kt][3]);
        }

        float oc[8][4];
#pragma unroll
        for (int dt = 0; dt < 8; dt++)
#pragma unroll
            for (int e = 0; e < 4; e++) oc[dt][e] = 0.f;

#pragma unroll
        for (int dtp = 0; dtp < 4; dtp++) {
            const int vrow = dtp * 16 + (idx >> 1) * 8 + (lane & 7);
            const int vcol = (idx & 1) * 8;
#pragma unroll
            for (int kt = 0; kt < 13; kt++) {
                uint32_t vh[4], vl[4];
                ldsm_x4(vh, smem_u32(VTH + vrow * VTS + kt * 16 + vcol));
                ldsm_x4(vl, smem_u32(VTL + vrow * VTS + kt * 16 + vcol));
                mma_f16(oc[2 * dtp],     ph[kt], &vh[0]);
                mma_f16(oc[2 * dtp + 1], ph[kt], &vh[2]);
                mma_f16(oc[2 * dtp],     pl[kt], &vh[0]);
                mma_f16(oc[2 * dtp + 1], pl[kt], &vh[2]);
                mma_f16(oc[2 * dtp],     ph[kt], &vl[0]);
                mma_f16(oc[2 * dtp + 1], ph[kt], &vl[2]);
            }
        }

        // store: split into hi/lo fp16 planes directly (proj GEMM A operand)
#pragma unroll
        for (int dt = 0; dt < 8; dt++) {
            const int d0 = dt * 8 + 2 * t;
            if (va) {
                uint32_t hb, lb;
                pack2(oc[dt][0], oc[dt][1], hb, lb);
                const size_t ei = (((size_t)b * NQ + qa) * CDIM + h * HD + d0) >> 1;
                ohi[ei] = hb; olo[ei] = lb;
            }
            if (vb) {
                uint32_t hb, lb;
                pack2(oc[dt][2], oc[dt][3], hb, lb);
                const size_t ei = (((size_t)b * NQ + qb) * CDIM + h * HD + d0) >> 1;
                ohi[ei] = hb; olo[ei] = lb;
            }
        }
    }
}

// ===========================================================================
extern "C" void kernel_launch(void* const* d_in, const int* in_sizes, int n_in,
                              void* d_out, int out_size)
{
    const float* x      = (const float*)d_in[0];
    const float* w_qkv  = (const float*)d_in[1];
    const float* w_proj = (const float*)d_in[2];
    const float* b_proj = (const float*)d_in[3];
    const float* rpb    = (const float*)d_in[4];
    const int*   relidx = (const int*)d_in[5];
    float* out = (float*)d_out;

    float* qkv_s;
    __half2 *xhi, *xlo, *whi, *wlo, *phi, *plo, *ahi, *alo;
    cudaGetSymbolAddress((void**)&qkv_s, g_qkv);
    cudaGetSymbolAddress((void**)&xhi, g_xhi);
    cudaGetSymbolAddress((void**)&xlo, g_xlo);
    cudaGetSymbolAddress((void**)&whi, g_whi);
    cudaGetSymbolAddress((void**)&wlo, g_wlo);
    cudaGetSymbolAddress((void**)&phi, g_phi);
    cudaGetSymbolAddress((void**)&plo, g_plo);
    cudaGetSymbolAddress((void**)&ahi, g_ahi);
    cudaGetSymbolAddress((void**)&alo, g_alo);

    const int M = MTOT;   // 12608

    // 0) pre-split x, w_qkv, w_proj
    {
        int n4 = M * CDIM / 4;
        split_h<<<(n4 + 255) / 256, 256>>>((const float4*)x, xhi, xlo, n4);
        n4 = 3 * CDIM * CDIM / 4;
        split_h<<<(n4 + 255) / 256, 256>>>((const float4*)w_qkv, whi, wlo, n4);
        n4 = CDIM * CDIM / 4;
        split_h<<<(n4 + 255) / 256, 256>>>((const float4*)w_proj, phi, plo, n4);
    }

    cudaFuncSetAttribute(gemm_f16s4, cudaFuncAttributeMaxDynamicSharedMemorySize, G4SMEM);

    // 1) QKV GEMM: [M,768] x [2304,768]^T -> [M,2304]
    {
        dim3 grid((3 * CDIM) / 128, (M + 127) / 128);
        gemm_f16s4<<<grid, 256, G4SMEM>>>((const __half*)xhi, (const __half*)xlo,
                                          (const __half*)whi, (const __half*)wlo,
                                          nullptr, qkv_s, M, 3 * CDIM, CDIM);
    }

    // 2) attention (tensorized; emits split hi/lo planes directly)
    {
        cudaFuncSetAttribute(attn_mma, cudaFuncAttributeMaxDynamicSharedMemorySize,
                             ATM_SMEM);
        attn_mma<<<BATCH * NH, 256, ATM_SMEM>>>(qkv_s, rpb, relidx,
                                                (uint32_t*)ahi, (uint32_t*)alo);
    }

    // 3) proj GEMM: [M,768] x [768,768]^T + bias -> out
    {
        dim3 grid(CDIM / 128, (M + 127) / 128);
        gemm_f16s4<<<grid, 256, G4SMEM>>>((const __half*)ahi, (const __half*)alo,
                                          (const __half*)phi, (const __half*)plo,
                                          b_proj, out, M, CDIM, CDIM);
    }
}

// round 13
// speedup vs baseline: 1.5620x; 1.5620x over previous
#include <cuda_runtime.h>
#include <cuda_fp16.h>
#include <math_constants.h>
#include <cstdint>

// ---------------------------------------------------------------------------
// RPE_Attention: x[64,197,768] -> qkv -> per-head attention (+rel pos bias) ->
// proj.
// GEMMs: fp16 mma.sync TWO-term split  C = (Ahi+Alo)*Bhi  (A exact to 2^-22,
//        B carries fp16-rn error ~2e-4 RMS; total pipeline ~4-5e-4 < 1e-3).
//        R6-proven geometry: 128x128 tile, 8 warps (2x4), 64x32 warp tile,
//        BK=32, 2-stage cp.async, 2 CTAs/SM.
// Attention: tensorized mma.sync, 2-term (K,V hi-only), Q/P full split,
//            direct hi/lo split output for proj A-operand.
// ---------------------------------------------------------------------------

#define BATCH 64
#define NQ    197
#define CDIM  768
#define NH    12
#define HD    64
#define NP    196
#define MTOT  (BATCH * NQ)          // 12608

__device__ float   g_qkv[(size_t)MTOT * 3 * CDIM];
__device__ __half2 g_xhi[(size_t)MTOT * CDIM / 2];
__device__ __half2 g_xlo[(size_t)MTOT * CDIM / 2];
__device__ __half2 g_whi[(size_t)3 * CDIM * CDIM / 2];
__device__ __half2 g_phi[(size_t)CDIM * CDIM / 2];
__device__ __half2 g_ahi[(size_t)MTOT * CDIM / 2];
__device__ __half2 g_alo[(size_t)MTOT * CDIM / 2];

// ===========================================================================
// common helpers
// ===========================================================================
__device__ __forceinline__ unsigned smem_u32(const void* p) {
    return (unsigned)__cvta_generic_to_shared(p);
}
__device__ __forceinline__ void cp_async16(unsigned dst, const void* src, bool pred) {
    int sz = pred ? 16 : 0;
    asm volatile("cp.async.cg.shared.global [%0], [%1], 16, %2;\n"
                 :: "r"(dst), "l"(src), "r"(sz));
}
__device__ __forceinline__ void cp_commit() { asm volatile("cp.async.commit_group;\n"); }
__device__ __forceinline__ void cp_wait0()  { asm volatile("cp.async.wait_group 0;\n"); }

__device__ __forceinline__ void ldsm_x4(uint32_t* r, unsigned a) {
    asm volatile("ldmatrix.sync.aligned.m8n8.x4.shared.b16 {%0,%1,%2,%3}, [%4];"
                 : "=r"(r[0]), "=r"(r[1]), "=r"(r[2]), "=r"(r[3]) : "r"(a));
}
__device__ __forceinline__ void ldsm_x2(uint32_t& r0, uint32_t& r1, unsigned a) {
    asm volatile("ldmatrix.sync.aligned.m8n8.x2.shared.b16 {%0,%1}, [%2];"
                 : "=r"(r0), "=r"(r1) : "r"(a));
}
__device__ __forceinline__ void mma_f16(float* d, const uint32_t* a, const uint32_t* b) {
    asm volatile(
        "mma.sync.aligned.m16n8k16.row.col.f32.f16.f16.f32 "
        "{%0,%1,%2,%3}, {%4,%5,%6,%7}, {%8,%9}, {%0,%1,%2,%3};"
        : "+f"(d[0]), "+f"(d[1]), "+f"(d[2]), "+f"(d[3])
        : "r"(a[0]), "r"(a[1]), "r"(a[2]), "r"(a[3]), "r"(b[0]), "r"(b[1]));
}

// ===========================================================================
// splits: fp32 -> fp16 planes
// ===========================================================================
__global__ void split_h(const float4* __restrict__ src, __half2* __restrict__ hi,
                        __half2* __restrict__ lo, int n4)
{
    int i = blockIdx.x * blockDim.x + threadIdx.x;
    if (i >= n4) return;
    float4 v = src[i];
    __half2 h0 = __floats2half2_rn(v.x, v.y);
    __half2 h1 = __floats2half2_rn(v.z, v.w);
    float2 f0 = __half22float2(h0);
    float2 f1 = __half22float2(h1);
    hi[2 * i]     = h0;
    hi[2 * i + 1] = h1;
    lo[2 * i]     = __floats2half2_rn(v.x - f0.x, v.y - f0.y);
    lo[2 * i + 1] = __floats2half2_rn(v.z - f1.x, v.w - f1.y);
}

__global__ void split_hi_only(const float4* __restrict__ src,
                              __half2* __restrict__ hi, int n4)
{
    int i = blockIdx.x * blockDim.x + threadIdx.x;
    if (i >= n4) return;
    float4 v = src[i];
    hi[2 * i]     = __floats2half2_rn(v.x, v.y);
    hi[2 * i + 1] = __floats2half2_rn(v.z, v.w);
}

// ===========================================================================
// 2-term fp16 GEMM (NT): C = (Ahi+Alo) * Bhi^T (+bias)
// BM=BN=128, BK=32, 256 thr = 8 warps (2x4), warp tile 64x32.
// SMEM: [Abuf0 hi,lo][Abuf1 hi,lo][Bbuf0 hi][Bbuf1 hi], row stride 40 halfs.
// ===========================================================================
#define APAD   40
#define PLANE  (128 * APAD)            // 5120 halfs
#define ABUF   (2 * PLANE)             // A hi+lo per buffer
#define BBASE  (2 * ABUF)              // 20480 halfs: B region start
#define GSMEM  ((4 * PLANE + 2 * PLANE) * 2)   // 61440 bytes

__global__ __launch_bounds__(256, 2) void gemm_2t(
    const __half* __restrict__ Ahi, const __half* __restrict__ Alo,
    const __half* __restrict__ Bhi,
    const float* __restrict__ bias, float* __restrict__ C,
    int M, int N, int K)
{
    extern __shared__ __half smg[];

    const int tid  = threadIdx.x;
    const int lane = tid & 31;
    const int wid  = tid >> 5;
    const int wm   = wid & 1;          // 64-row band
    const int wn   = wid >> 1;         // 32-col band (0..3)
    const int bm   = blockIdx.y * 128;
    const int bn   = blockIdx.x * 128;

    // loader: thread -> half a row (16 halfs = 32B) per plane
    const int lrow = tid >> 1;
    const int lcol = (tid & 1) * 16;
    const bool aok = (bm + lrow) < M;
    const __half* gA0 = Ahi + (size_t)(aok ? bm + lrow : 0) * K + lcol;
    const __half* gA1 = Alo + (size_t)(aok ? bm + lrow : 0) * K + lcol;
    const __half* gB0 = Bhi + (size_t)(bn + lrow) * K + lcol;

    const unsigned a0Addr = smem_u32(smg) + (unsigned)(lrow * APAD + lcol) * 2u;
    const unsigned a1Addr = a0Addr + PLANE * 2;
    const unsigned bAddr  = smem_u32(smg) + (unsigned)(BBASE + lrow * APAD + lcol) * 2u;
    const unsigned ABUFB  = ABUF * 2;   // byte stride between A buffers
    const unsigned BBUFB  = PLANE * 2;  // byte stride between B buffers

    const int nIter = K / 32;          // 24

    float acc[4][4][4];
#pragma unroll
    for (int i = 0; i < 4; i++)
#pragma unroll
        for (int j = 0; j < 4; j++)
#pragma unroll
            for (int r = 0; r < 4; r++) acc[i][j][r] = 0.f;

    // prologue
    {
        cp_async16(a0Addr,      gA0,     aok);
        cp_async16(a0Addr + 16, gA0 + 8, aok);
        cp_async16(a1Addr,      gA1,     aok);
        cp_async16(a1Addr + 16, gA1 + 8, aok);
        cp_async16(bAddr,       gB0,     true);
        cp_async16(bAddr + 16,  gB0 + 8, true);
        cp_commit();
    }

    for (int it = 0; it < nIter; it++) {
        cp_wait0();
        __syncthreads();

        if (it + 1 < nIter) {
            const int k0 = (it + 1) * 32;
            const unsigned ao = (unsigned)((it + 1) & 1) * ABUFB;
            const unsigned bo = (unsigned)((it + 1) & 1) * BBUFB;
            cp_async16(a0Addr + ao,      gA0 + k0,     aok);
            cp_async16(a0Addr + ao + 16, gA0 + k0 + 8, aok);
            cp_async16(a1Addr + ao,      gA1 + k0,     aok);
            cp_async16(a1Addr + ao + 16, gA1 + k0 + 8, aok);
            cp_async16(bAddr + bo,       gB0 + k0,     true);
            cp_async16(bAddr + bo + 16,  gB0 + k0 + 8, true);
            cp_commit();
        }

        const __half* sa0 = smg + (it & 1) * ABUF;
        const __half* sa1 = sa0 + PLANE;
        const __half* sb  = smg + BBASE + (it & 1) * PLANE;

#pragma unroll
        for (int ks = 0; ks < 2; ks++) {
            uint32_t bh[4][2];
#pragma unroll
            for (int nt = 0; nt < 4; nt++) {
                const int row = wn * 32 + nt * 8 + (lane & 7);
                const int col = ks * 16 + ((lane >> 3) & 1) * 8;
                ldsm_x2(bh[nt][0], bh[nt][1], smem_u32(sb + row * APAD + col));
            }
#pragma unroll
            for (int mt = 0; mt < 4; mt++) {
                const int row = wm * 64 + mt * 16 + (lane & 15);
                const int col = ks * 16 + (lane >> 4) * 8;
                uint32_t ah[4], al[4];
                ldsm_x4(ah, smem_u32(sa0 + row * APAD + col));
                ldsm_x4(al, smem_u32(sa1 + row * APAD + col));
#pragma unroll
                for (int nt = 0; nt < 4; nt++) mma_f16(acc[mt][nt], ah, bh[nt]);
#pragma unroll
                for (int nt = 0; nt < 4; nt++) mma_f16(acc[mt][nt], al, bh[nt]);
            }
        }
    }

    // epilogue
    const int g = lane >> 2;
    const int t = lane & 3;
#pragma unroll
    for (int mt = 0; mt < 4; mt++) {
        const int r0 = bm + wm * 64 + mt * 16 + g;
#pragma unroll
        for (int nt = 0; nt < 4; nt++) {
            const int col = bn + wn * 32 + nt * 8 + 2 * t;
            const float bv0 = bias ? bias[col]     : 0.f;
            const float bv1 = bias ? bias[col + 1] : 0.f;
            if (r0 < M) {
                float2 v = make_float2(acc[mt][nt][0] + bv0, acc[mt][nt][1] + bv1);
                *(float2*)&C[(size_t)r0 * N + col] = v;
            }
            if (r0 + 8 < M) {
                float2 v = make_float2(acc[mt][nt][2] + bv0, acc[mt][nt][3] + bv1);
                *(float2*)&C[(size_t)(r0 + 8) * N + col] = v;
            }
        }
    }
}

// ===========================================================================
// Tensorized attention, 2-term: K and V hi-only; Q and P fully split.
// Block per (b,h), 256 threads = 8 warps; warp owns m-tiles of 16 q rows.
// Output stored directly as hi/lo fp16 planes (proj A operand).
// ===========================================================================
#define NPAD   208
#define QKS    72
#define VTS    232
#define QH_OFF 0
#define QL_OFF (NPAD * QKS)            // 14976
#define KH_OFF (2 * NPAD * QKS)        // 29952
#define VTH_OFF (3 * NPAD * QKS)       // 44928
#define ATM_HALFS (VTH_OFF + HD * VTS) // 59776
#define ATM_SMEM  (ATM_HALFS * 2 + 736 * 4)   // 122496 bytes

__device__ __forceinline__ void pack2(float x, float y, uint32_t& hi, uint32_t& lo) {
    __half2 h = __floats2half2_rn(x, y);
    float2 f = __half22float2(h);
    __half2 l = __floats2half2_rn(x - f.x, y - f.y);
    hi = *reinterpret_cast<uint32_t*>(&h);
    lo = *reinterpret_cast<uint32_t*>(&l);
}

__global__ __launch_bounds__(256, 1) void attn_mma2(
    const float* __restrict__ qkv, const float* __restrict__ rpb_table,
    const int* __restrict__ rel_idx,
    uint32_t* __restrict__ ohi, uint32_t* __restrict__ olo)
{
    extern __shared__ __align__(16) __half sma[];
    __half* QH  = sma + QH_OFF;
    __half* QL  = sma + QL_OFF;
    __half* KH  = sma + KH_OFF;
    __half* VTH = sma + VTH_OFF;
    float*  bias_s = (float*)(sma + ATM_HALFS);

    const int tid  = threadIdx.x;
    const int lane = tid & 31;
    const int wid  = tid >> 5;
    const int b = blockIdx.x / NH;
    const int h = blockIdx.x % NH;

    // ---- load: Q split hi/lo (scaled), K hi, V^T hi ----
    const float* base0 = qkv + (size_t)b * NQ * (3 * CDIM) + h * HD;
    for (int i = tid; i < NPAD * HD; i += 256) {
        const int n = i >> 6, d = i & 63;
        float qv = 0.f, kv = 0.f, vv = 0.f;
        if (n < NQ) {
            const float* p = base0 + (size_t)n * (3 * CDIM) + d;
            qv = p[0] * 0.125f;
            kv = p[CDIM];
            vv = p[2 * CDIM];
        }
        __half qh_ = __float2half_rn(qv);
        QH[n * QKS + d] = qh_;
        QL[n * QKS + d] = __float2half_rn(qv - __half2float(qh_));
        KH[n * QKS + d] = __float2half_rn(kv);
        VTH[d * VTS + n] = __float2half_rn(vv);
    }
    for (int i = tid; i < 729; i += 256) bias_s[i] = rpb_table[i * NH + h];
    __syncthreads();

    const int g = lane >> 2;
    const int t = lane & 3;
    const int idx = lane >> 3;

    for (int mt = wid; mt < 13; mt += 8) {
        const int q0 = mt * 16;

        uint32_t qfh[4][4], qfl[4][4];
        {
            const int row = q0 + (lane & 15);
            const int col = (lane >> 4) * 8;
#pragma unroll
            for (int kt = 0; kt < 4; kt++) {
                ldsm_x4(qfh[kt], smem_u32(QH + row * QKS + kt * 16 + col));
                ldsm_x4(qfl[kt], smem_u32(QL + row * QKS + kt * 16 + col));
            }
        }

        // ---- scores: S[16 x 208], 2-term ----
        float sc[26][4];
#pragma unroll
        for (int nt = 0; nt < 26; nt++)
#pragma unroll
            for (int e = 0; e < 4; e++) sc[nt][e] = 0.f;

#pragma unroll
        for (int ntp = 0; ntp < 13; ntp++) {
            const int row = ntp * 16 + (idx >> 1) * 8 + (lane & 7);
            const int col = (idx & 1) * 8;
            uint32_t kf[4][4];
#pragma unroll
            for (int kt = 0; kt < 4; kt++)
                ldsm_x4(kf[kt], smem_u32(KH + row * QKS + kt * 16 + col));
#pragma unroll
            for (int kt = 0; kt < 4; kt++) {
                mma_f16(sc[2 * ntp],     qfh[kt], &kf[kt][0]);
                mma_f16(sc[2 * ntp + 1], qfh[kt], &kf[kt][2]);
                mma_f16(sc[2 * ntp],     qfl[kt], &kf[kt][0]);
                mma_f16(sc[2 * ntp + 1], qfl[kt], &kf[kt][2]);
            }
        }

        // ---- bias + mask ----
        const int qa = q0 + g;
        const int qb = q0 + g + 8;
        const bool va = qa < NQ;
        const bool vb = qb < NQ;
#pragma unroll
        for (int nt = 0; nt < 26; nt++) {
            const int j0 = nt * 8 + 2 * t;
            const int j1 = j0 + 1;
            {
                float s = sc[nt][0];
                if (!va) s = 0.f;
                else if (j0 >= NQ) s = -CUDART_INF_F;
                else if (qa > 0 && j0 > 0)
                    s += bias_s[__ldg(rel_idx + (qa - 1) * NP + (j0 - 1))];
                sc[nt][0] = s;
            }
            {
                float s = sc[nt][1];
                if (!va) s = 0.f;
                else if (j1 >= NQ) s = -CUDART_INF_F;
                else if (qa > 0)
                    s += bias_s[__ldg(rel_idx + (qa - 1) * NP + (j1 - 1))];
                sc[nt][1] = s;
            }
            {
                float s = sc[nt][2];
                if (!vb) s = 0.f;
                else if (j0 >= NQ) s = -CUDART_INF_F;
                else if (qb > 0 && j0 > 0)
                    s += bias_s[__ldg(rel_idx + (qb - 1) * NP + (j0 - 1))];
                sc[nt][2] = s;
            }
            {
                float s = sc[nt][3];
                if (!vb) s = 0.f;
                else if (j1 >= NQ) s = -CUDART_INF_F;
                else if (qb > 0)
                    s += bias_s[__ldg(rel_idx + (qb - 1) * NP + (j1 - 1))];
                sc[nt][3] = s;
            }
        }

        // ---- softmax (rows qa, qb on lane group {4g..4g+3}) ----
        float mA = -CUDART_INF_F, mB = -CUDART_INF_F;
#pragma unroll
        for (int nt = 0; nt < 26; nt++) {
            mA = fmaxf(mA, fmaxf(sc[nt][0], sc[nt][1]));
            mB = fmaxf(mB, fmaxf(sc[nt][2], sc[nt][3]));
        }
        mA = fmaxf(mA, __shfl_xor_sync(0xffffffffu, mA, 1));
        mA = fmaxf(mA, __shfl_xor_sync(0xffffffffu, mA, 2));
        mB = fmaxf(mB, __shfl_xor_sync(0xffffffffu, mB, 1));
        mB = fmaxf(mB, __shfl_xor_sync(0xffffffffu, mB, 2));

        float eA = 0.f, eB = 0.f;
#pragma unroll
        for (int nt = 0; nt < 26; nt++) {
            sc[nt][0] = __expf(sc[nt][0] - mA);
            sc[nt][1] = __expf(sc[nt][1] - mA);
            sc[nt][2] = __expf(sc[nt][2] - mB);
            sc[nt][3] = __expf(sc[nt][3] - mB);
            eA += sc[nt][0] + sc[nt][1];
            eB += sc[nt][2] + sc[nt][3];
        }
        eA += __shfl_xor_sync(0xffffffffu, eA, 1);
        eA += __shfl_xor_sync(0xffffffffu, eA, 2);
        eB += __shfl_xor_sync(0xffffffffu, eB, 1);
        eB += __shfl_xor_sync(0xffffffffu, eB, 2);
        const float invA = 1.f / eA;
        const float invB = 1.f / eB;

        // ---- P -> split fp16 A-fragments (P stays exact to 2^-22) ----
        uint32_t ph[13][4], pl[13][4];
#pragma unroll
        for (int kt = 0; kt < 13; kt++) {
            pack2(sc[2 * kt][0] * invA,     sc[2 * kt][1] * invA,     ph[kt][0], pl[kt][0]);
            pack2(sc[2 * kt][2] * invB,     sc[2 * kt][3] * invB,     ph[kt][1], pl[kt][1]);
            pack2(sc[2 * kt + 1][0] * invA, sc[2 * kt + 1][1] * invA, ph[kt][2], pl[kt][2]);
            pack2(sc[2 * kt + 1][2] * invB, sc[2 * kt + 1][3] * invB, ph[kt][3], pl[kt][3]);
        }

        // ---- PV: O[16 x 64], 2-term ----
        float oc[8][4];
#pragma unroll
        for (int dt = 0; dt < 8; dt++)
#pragma unroll
            for (int e = 0; e < 4; e++) oc[dt][e] = 0.f;

#pragma unroll
        for (int dtp = 0; dtp < 4; dtp++) {
            const int vrow = dtp * 16 + (idx >> 1) * 8 + (lane & 7);
            const int vcol = (idx & 1) * 8;
#pragma unroll
            for (int kt = 0; kt < 13; kt++) {
                uint32_t vh[4];
                ldsm_x4(vh, smem_u32(VTH + vrow * VTS + kt * 16 + vcol));
                mma_f16(oc[2 * dtp],     ph[kt], &vh[0]);
                mma_f16(oc[2 * dtp + 1], ph[kt], &vh[2]);
                mma_f16(oc[2 * dtp],     pl[kt], &vh[0]);
                mma_f16(oc[2 * dtp + 1], pl[kt], &vh[2]);
            }
        }

        // ---- store: split hi/lo planes (proj A operand) ----
#pragma unroll
        for (int dt = 0; dt < 8; dt++) {
            const int d0 = dt * 8 + 2 * t;
            if (va) {
                uint32_t hb, lb;
                pack2(oc[dt][0], oc[dt][1], hb, lb);
                const size_t ei = (((size_t)b * NQ + qa) * CDIM + h * HD + d0) >> 1;
                ohi[ei] = hb; olo[ei] = lb;
            }
            if (vb) {
                uint32_t hb, lb;
                pack2(oc[dt][2], oc[dt][3], hb, lb);
                const size_t ei = (((size_t)b * NQ + qb) * CDIM + h * HD + d0) >> 1;
                ohi[ei] = hb; olo[ei] = lb;
            }
        }
    }
}

// ===========================================================================
extern "C" void kernel_launch(void* const* d_in, const int* in_sizes, int n_in,
                              void* d_out, int out_size)
{
    const float* x      = (const float*)d_in[0];
    const float* w_qkv  = (const float*)d_in[1];
    const float* w_proj = (const float*)d_in[2];
    const float* b_proj = (const float*)d_in[3];
    const float* rpb    = (const float*)d_in[4];
    const int*   relidx = (const int*)d_in[5];
    float* out = (float*)d_out;

    float* qkv_s;
    __half2 *xhi, *xlo, *whi, *phi, *ahi, *alo;
    cudaGetSymbolAddress((void**)&qkv_s, g_qkv);
    cudaGetSymbolAddress((void**)&xhi, g_xhi);
    cudaGetSymbolAddress((void**)&xlo, g_xlo);
    cudaGetSymbolAddress((void**)&whi, g_whi);
    cudaGetSymbolAddress((void**)&phi, g_phi);
    cudaGetSymbolAddress((void**)&ahi, g_ahi);
    cudaGetSymbolAddress((void**)&alo, g_alo);

    const int M = MTOT;   // 12608

    // 0) pre-split: x -> hi+lo (A side), weights -> hi only (B side)
    {
        int n4 = M * CDIM / 4;
        split_h<<<(n4 + 255) / 256, 256>>>((const float4*)x, xhi, xlo, n4);
        n4 = 3 * CDIM * CDIM / 4;
        split_hi_only<<<(n4 + 255) / 256, 256>>>((const float4*)w_qkv, whi, n4);
        n4 = CDIM * CDIM / 4;
        split_hi_only<<<(n4 + 255) / 256, 256>>>((const float4*)w_proj, phi, n4);
    }

    cudaFuncSetAttribute(gemm_2t, cudaFuncAttributeMaxDynamicSharedMemorySize, GSMEM);

    // 1) QKV GEMM: [M,768] x [2304,768]^T -> [M,2304]
    {
        dim3 grid((3 * CDIM) / 128, (M + 127) / 128);
        gemm_2t<<<grid, 256, GSMEM>>>((const __half*)xhi, (const __half*)xlo,
                                      (const __half*)whi,
                                      nullptr, qkv_s, M, 3 * CDIM, CDIM);
    }

    // 2) attention (tensorized, 2-term; emits split hi/lo planes)
    {
        cudaFuncSetAttribute(attn_mma2, cudaFuncAttributeMaxDynamicSharedMemorySize,
                             ATM_SMEM);
        attn_mma2<<<BATCH * NH, 256, ATM_SMEM>>>(qkv_s, rpb, relidx,
                                                 (uint32_t*)ahi, (uint32_t*)alo);
    }

    // 3) proj GEMM: [M,768] x [768,768]^T + bias -> out
    {
        dim3 grid(CDIM / 128, (M + 127) / 128);
        gemm_2t<<<grid, 256, GSMEM>>>((const __half*)ahi, (const __half*)alo,
                                      (const __half*)phi,
                                      b_proj, out, M, CDIM, CDIM);
    }
}

// round 17
// speedup vs baseline: 2.1087x; 1.3500x over previous
#include <cuda_runtime.h>
#include <cuda_fp16.h>
#include <math_constants.h>
#include <cstdint>

// ---------------------------------------------------------------------------
// RPE_Attention: x[64,197,768] -> qkv -> per-head attention (+rel pos bias) ->
// proj.
// GEMMs: pure fp16 mma.sync (A hi, B hi).  Error ~3e-4 RMS (quadrature of
//        both-side fp16 rounding), well under 1e-3.
// Attention: scores keep 2-term Q split (softmax sensitivity); PV 1-term;
//            output hi-only fp16 plane for proj A-operand.
// ---------------------------------------------------------------------------

#define BATCH 64
#define NQ    197
#define CDIM  768
#define NH    12
#define HD    64
#define NP    196
#define MTOT  (BATCH * NQ)          // 12608

__device__ float   g_qkv[(size_t)MTOT * 3 * CDIM];
__device__ __half2 g_xhi[(size_t)MTOT * CDIM / 2];
__device__ __half2 g_whi[(size_t)3 * CDIM * CDIM / 2];
__device__ __half2 g_phi[(size_t)CDIM * CDIM / 2];
__device__ __half2 g_ahi[(size_t)MTOT * CDIM / 2];

// ===========================================================================
// common helpers
// ===========================================================================
__device__ __forceinline__ unsigned smem_u32(const void* p) {
    return (unsigned)__cvta_generic_to_shared(p);
}
__device__ __forceinline__ void cp_async16(unsigned dst, const void* src, bool pred) {
    int sz = pred ? 16 : 0;
    asm volatile("cp.async.cg.shared.global [%0], [%1], 16, %2;\n"
                 :: "r"(dst), "l"(src), "r"(sz));
}
__device__ __forceinline__ void cp_commit() { asm volatile("cp.async.commit_group;\n"); }
__device__ __forceinline__ void cp_wait0()  { asm volatile("cp.async.wait_group 0;\n"); }

__device__ __forceinline__ void ldsm_x4(uint32_t* r, unsigned a) {
    asm volatile("ldmatrix.sync.aligned.m8n8.x4.shared.b16 {%0,%1,%2,%3}, [%4];"
                 : "=r"(r[0]), "=r"(r[1]), "=r"(r[2]), "=r"(r[3]) : "r"(a));
}
__device__ __forceinline__ void ldsm_x2(uint32_t& r0, uint32_t& r1, unsigned a) {
    asm volatile("ldmatrix.sync.aligned.m8n8.x2.shared.b16 {%0,%1}, [%2];"
                 : "=r"(r0), "=r"(r1) : "r"(a));
}
__device__ __forceinline__ void mma_f16(float* d, const uint32_t* a, const uint32_t* b) {
    asm volatile(
        "mma.sync.aligned.m16n8k16.row.col.f32.f16.f16.f32 "
        "{%0,%1,%2,%3}, {%4,%5,%6,%7}, {%8,%9}, {%0,%1,%2,%3};"
        : "+f"(d[0]), "+f"(d[1]), "+f"(d[2]), "+f"(d[3])
        : "r"(a[0]), "r"(a[1]), "r"(a[2]), "r"(a[3]), "r"(b[0]), "r"(b[1]));
}

// ===========================================================================
// split: fp32 -> fp16 hi plane
// ===========================================================================
__global__ void split_hi_only(const float4* __restrict__ src,
                              __half2* __restrict__ hi, int n4)
{
    int i = blockIdx.x * blockDim.x + threadIdx.x;
    if (i >= n4) return;
    float4 v = src[i];
    hi[2 * i]     = __floats2half2_rn(v.x, v.y);
    hi[2 * i + 1] = __floats2half2_rn(v.z, v.w);
}

// ===========================================================================
// fp16 GEMM (NT): C = Ahi * Bhi^T (+bias)
// BM=BN=128, BK=32, 256 thr = 8 warps (2x4), warp tile 64x32, 2-stage.
// SMEM: [A0][A1][B0][B1], row stride 40 halfs.  40960 bytes total.
// ===========================================================================
#define APAD   40
#define PLANE  (128 * APAD)            // 5120 halfs
#define BBASE  (2 * PLANE)             // B region start (halfs)
#define GSMEM  (4 * PLANE * 2)         // 40960 bytes

__global__ __launch_bounds__(256, 2) void gemm_1t(
    const __half* __restrict__ Ahi, const __half* __restrict__ Bhi,
    const float* __restrict__ bias, float* __restrict__ C,
    int M, int N, int K)
{
    extern __shared__ __half smg[];

    const int tid  = threadIdx.x;
    const int lane = tid & 31;
    const int wid  = tid >> 5;
    const int wm   = wid & 1;          // 64-row band
    const int wn   = wid >> 1;         // 32-col band (0..3)
    const int bm   = blockIdx.y * 128;
    const int bn   = blockIdx.x * 128;

    const int lrow = tid >> 1;
    const int lcol = (tid & 1) * 16;
    const bool aok = (bm + lrow) < M;
    const __half* gA = Ahi + (size_t)(aok ? bm + lrow : 0) * K + lcol;
    const __half* gB = Bhi + (size_t)(bn + lrow) * K + lcol;

    const unsigned aAddr = smem_u32(smg) + (unsigned)(lrow * APAD + lcol) * 2u;
    const unsigned bAddr = smem_u32(smg) + (unsigned)(BBASE + lrow * APAD + lcol) * 2u;
    const unsigned BUFB  = PLANE * 2;   // byte stride between buffers

    const int nIter = K / 32;          // 24

    float acc[4][4][4];
#pragma unroll
    for (int i = 0; i < 4; i++)
#pragma unroll
        for (int j = 0; j < 4; j++)
#pragma unroll
            for (int r = 0; r < 4; r++) acc[i][j][r] = 0.f;

    {
        cp_async16(aAddr,      gA,     aok);
        cp_async16(aAddr + 16, gA + 8, aok);
        cp_async16(bAddr,      gB,     true);
        cp_async16(bAddr + 16, gB + 8, true);
        cp_commit();
    }

    for (int it = 0; it < nIter; it++) {
        cp_wait0();
        __syncthreads();

        if (it + 1 < nIter) {
            const int k0 = (it + 1) * 32;
            const unsigned off = (unsigned)((it + 1) & 1) * BUFB;
            cp_async16(aAddr + off,      gA + k0,     aok);
            cp_async16(aAddr + off + 16, gA + k0 + 8, aok);
            cp_async16(bAddr + off,      gB + k0,     true);
            cp_async16(bAddr + off + 16, gB + k0 + 8, true);
            cp_commit();
        }

        const __half* sa = smg + (it & 1) * PLANE;
        const __half* sb = smg + BBASE + (it & 1) * PLANE;

#pragma unroll
        for (int ks = 0; ks < 2; ks++) {
            uint32_t bh[4][2];
#pragma unroll
            for (int nt = 0; nt < 4; nt++) {
                const int row = wn * 32 + nt * 8 + (lane & 7);
                const int col = ks * 16 + ((lane >> 3) & 1) * 8;
                ldsm_x2(bh[nt][0], bh[nt][1], smem_u32(sb + row * APAD + col));
            }
#pragma unroll
            for (int mt = 0; mt < 4; mt++) {
                const int row = wm * 64 + mt * 16 + (lane & 15);
                const int col = ks * 16 + (lane >> 4) * 8;
                uint32_t ah[4];
                ldsm_x4(ah, smem_u32(sa + row * APAD + col));
#pragma unroll
                for (int nt = 0; nt < 4; nt++) mma_f16(acc[mt][nt], ah, bh[nt]);
            }
        }
    }

    // epilogue
    const int g = lane >> 2;
    const int t = lane & 3;
#pragma unroll
    for (int mt = 0; mt < 4; mt++) {
        const int r0 = bm + wm * 64 + mt * 16 + g;
#pragma unroll
        for (int nt = 0; nt < 4; nt++) {
            const int col = bn + wn * 32 + nt * 8 + 2 * t;
            const float bv0 = bias ? bias[col]     : 0.f;
            const float bv1 = bias ? bias[col + 1] : 0.f;
            if (r0 < M) {
                float2 v = make_float2(acc[mt][nt][0] + bv0, acc[mt][nt][1] + bv1);
                *(float2*)&C[(size_t)r0 * N + col] = v;
            }
            if (r0 + 8 < M) {
                float2 v = make_float2(acc[mt][nt][2] + bv0, acc[mt][nt][3] + bv1);
                *(float2*)&C[(size_t)(r0 + 8) * N + col] = v;
            }
        }
    }
}

// ===========================================================================
// Tensorized attention: scores 2-term (Q hi/lo vs K hi), PV 1-term (P hi vs
// V hi).  Block per (b,h), 256 threads.  Output: hi-only fp16 plane.
// ===========================================================================
#define NPAD   208
#define QKS    72
#define VTS    232
#define QH_OFF 0
#define QL_OFF (NPAD * QKS)            // 14976
#define KH_OFF (2 * NPAD * QKS)        // 29952
#define VTH_OFF (3 * NPAD * QKS)       // 44928
#define ATM_HALFS (VTH_OFF + HD * VTS) // 59776
#define ATM_SMEM  (ATM_HALFS * 2 + 736 * 4)   // 122496 bytes

__global__ __launch_bounds__(256, 1) void attn_mma3(
    const float* __restrict__ qkv, const float* __restrict__ rpb_table,
    const int* __restrict__ rel_idx, uint32_t* __restrict__ ohi)
{
    extern __shared__ __align__(16) __half sma[];
    __half* QH  = sma + QH_OFF;
    __half* QL  = sma + QL_OFF;
    __half* KH  = sma + KH_OFF;
    __half* VTH = sma + VTH_OFF;
    float*  bias_s = (float*)(sma + ATM_HALFS);

    const int tid  = threadIdx.x;
    const int lane = tid & 31;
    const int wid  = tid >> 5;
    const int b = blockIdx.x / NH;
    const int h = blockIdx.x % NH;

    const float* base0 = qkv + (size_t)b * NQ * (3 * CDIM) + h * HD;
    for (int i = tid; i < NPAD * HD; i += 256) {
        const int n = i >> 6, d = i & 63;
        float qv = 0.f, kv = 0.f, vv = 0.f;
        if (n < NQ) {
            const float* p = base0 + (size_t)n * (3 * CDIM) + d;
            qv = p[0] * 0.125f;
            kv = p[CDIM];
            vv = p[2 * CDIM];
        }
        __half qh_ = __float2half_rn(qv);
        QH[n * QKS + d] = qh_;
        QL[n * QKS + d] = __float2half_rn(qv - __half2float(qh_));
        KH[n * QKS + d] = __float2half_rn(kv);
        VTH[d * VTS + n] = __float2half_rn(vv);
    }
    for (int i = tid; i < 729; i += 256) bias_s[i] = rpb_table[i * NH + h];
    __syncthreads();

    const int g = lane >> 2;
    const int t = lane & 3;
    const int idx = lane >> 3;

    for (int mt = wid; mt < 13; mt += 8) {
        const int q0 = mt * 16;

        uint32_t qfh[4][4], qfl[4][4];
        {
            const int row = q0 + (lane & 15);
            const int col = (lane >> 4) * 8;
#pragma unroll
            for (int kt = 0; kt < 4; kt++) {
                ldsm_x4(qfh[kt], smem_u32(QH + row * QKS + kt * 16 + col));
                ldsm_x4(qfl[kt], smem_u32(QL + row * QKS + kt * 16 + col));
            }
        }

        // ---- scores: S[16 x 208], 2-term on Q ----
        float sc[26][4];
#pragma unroll
        for (int nt = 0; nt < 26; nt++)
#pragma unroll
            for (int e = 0; e < 4; e++) sc[nt][e] = 0.f;

#pragma unroll
        for (int ntp = 0; ntp < 13; ntp++) {
            const int row = ntp * 16 + (idx >> 1) * 8 + (lane & 7);
            const int col = (idx & 1) * 8;
            uint32_t kf[4][4];
#pragma unroll
            for (int kt = 0; kt < 4; kt++)
                ldsm_x4(kf[kt], smem_u32(KH + row * QKS + kt * 16 + col));
#pragma unroll
            for (int kt = 0; kt < 4; kt++) {
                mma_f16(sc[2 * ntp],     qfh[kt], &kf[kt][0]);
                mma_f16(sc[2 * ntp + 1], qfh[kt], &kf[kt][2]);
                mma_f16(sc[2 * ntp],     qfl[kt], &kf[kt][0]);
                mma_f16(sc[2 * ntp + 1], qfl[kt], &kf[kt][2]);
            }
        }

        // ---- bias + mask ----
        const int qa = q0 + g;
        const int qb = q0 + g + 8;
        const bool va = qa < NQ;
        const bool vb = qb < NQ;
#pragma unroll
        for (int nt = 0; nt < 26; nt++) {
            const int j0 = nt * 8 + 2 * t;
            const int j1 = j0 + 1;
            {
                float s = sc[nt][0];
                if (!va) s = 0.f;
                else if (j0 >= NQ) s = -CUDART_INF_F;
                else if (qa > 0 && j0 > 0)
                    s += bias_s[__ldg(rel_idx + (qa - 1) * NP + (j0 - 1))];
                sc[nt][0] = s;
            }
            {
                float s = sc[nt][1];
                if (!va) s = 0.f;
                else if (j1 >= NQ) s = -CUDART_INF_F;
                else if (qa > 0)
                    s += bias_s[__ldg(rel_idx + (qa - 1) * NP + (j1 - 1))];
                sc[nt][1] = s;
            }
            {
                float s = sc[nt][2];
                if (!vb) s = 0.f;
                else if (j0 >= NQ) s = -CUDART_INF_F;
                else if (qb > 0 && j0 > 0)
                    s += bias_s[__ldg(rel_idx + (qb - 1) * NP + (j0 - 1))];
                sc[nt][2] = s;
            }
            {
                float s = sc[nt][3];
                if (!vb) s = 0.f;
                else if (j1 >= NQ) s = -CUDART_INF_F;
                else if (qb > 0)
                    s += bias_s[__ldg(rel_idx + (qb - 1) * NP + (j1 - 1))];
                sc[nt][3] = s;
            }
        }

        // ---- softmax ----
        float mA = -CUDART_INF_F, mB = -CUDART_INF_F;
#pragma unroll
        for (int nt = 0; nt < 26; nt++) {
            mA = fmaxf(mA, fmaxf(sc[nt][0], sc[nt][1]));
            mB = fmaxf(mB, fmaxf(sc[nt][2], sc[nt][3]));
        }
        mA = fmaxf(mA, __shfl_xor_sync(0xffffffffu, mA, 1));
        mA = fmaxf(mA, __shfl_xor_sync(0xffffffffu, mA, 2));
        mB = fmaxf(mB, __shfl_xor_sync(0xffffffffu, mB, 1));
        mB = fmaxf(mB, __shfl_xor_sync(0xffffffffu, mB, 2));

        float eA = 0.f, eB = 0.f;
#pragma unroll
        for (int nt = 0; nt < 26; nt++) {
            sc[nt][0] = __expf(sc[nt][0] - mA);
            sc[nt][1] = __expf(sc[nt][1] - mA);
            sc[nt][2] = __expf(sc[nt][2] - mB);
            sc[nt][3] = __expf(sc[nt][3] - mB);
            eA += sc[nt][0] + sc[nt][1];
            eB += sc[nt][2] + sc[nt][3];
        }
        eA += __shfl_xor_sync(0xffffffffu, eA, 1);
        eA += __shfl_xor_sync(0xffffffffu, eA, 2);
        eB += __shfl_xor_sync(0xffffffffu, eB, 1);
        eB += __shfl_xor_sync(0xffffffffu, eB, 2);
        const float invA = 1.f / eA;
        const float invB = 1.f / eB;

        // ---- P -> fp16 A-fragments (hi only) ----
        uint32_t ph[13][4];
#pragma unroll
        for (int kt = 0; kt < 13; kt++) {
            __half2 v;
            v = __floats2half2_rn(sc[2 * kt][0] * invA, sc[2 * kt][1] * invA);
            ph[kt][0] = *reinterpret_cast<uint32_t*>(&v);
            v = __floats2half2_rn(sc[2 * kt][2] * invB, sc[2 * kt][3] * invB);
            ph[kt][1] = *reinterpret_cast<uint32_t*>(&v);
            v = __floats2half2_rn(sc[2 * kt + 1][0] * invA, sc[2 * kt + 1][1] * invA);
            ph[kt][2] = *reinterpret_cast<uint32_t*>(&v);
            v = __floats2half2_rn(sc[2 * kt + 1][2] * invB, sc[2 * kt + 1][3] * invB);
            ph[kt][3] = *reinterpret_cast<uint32_t*>(&v);
        }

        // ---- PV: O[16 x 64], 1-term ----
        float oc[8][4];
#pragma unroll
        for (int dt = 0; dt < 8; dt++)
#pragma unroll
            for (int e = 0; e < 4; e++) oc[dt][e] = 0.f;

#pragma unroll
        for (int dtp = 0; dtp < 4; dtp++) {
            const int vrow = dtp * 16 + (idx >> 1) * 8 + (lane & 7);
            const int vcol = (idx & 1) * 8;
#pragma unroll
            for (int kt = 0; kt < 13; kt++) {
                uint32_t vh[4];
                ldsm_x4(vh, smem_u32(VTH + vrow * VTS + kt * 16 + vcol));
                mma_f16(oc[2 * dtp],     ph[kt], &vh[0]);
                mma_f16(oc[2 * dtp + 1], ph[kt], &vh[2]);
            }
        }

        // ---- store: hi-only fp16 plane (proj A operand) ----
#pragma unroll
        for (int dt = 0; dt < 8; dt++) {
            const int d0 = dt * 8 + 2 * t;
            if (va) {
                __half2 v = __floats2half2_rn(oc[dt][0], oc[dt][1]);
                const size_t ei = (((size_t)b * NQ + qa) * CDIM + h * HD + d0) >> 1;
                ohi[ei] = *reinterpret_cast<uint32_t*>(&v);
            }
            if (vb) {
                __half2 v = __floats2half2_rn(oc[dt][2], oc[dt][3]);
                const size_t ei = (((size_t)b * NQ + qb) * CDIM + h * HD + d0) >> 1;
                ohi[ei] = *reinterpret_cast<uint32_t*>(&v);
            }
        }
    }
}

// ===========================================================================
extern "C" void kernel_launch(void* const* d_in, const int* in_sizes, int n_in,
                              void* d_out, int out_size)
{
    const float* x      = (const float*)d_in[0];
    const float* w_qkv  = (const float*)d_in[1];
    const float* w_proj = (const float*)d_in[2];
    const float* b_proj = (const float*)d_in[3];
    const float* rpb    = (const float*)d_in[4];
    const int*   relidx = (const int*)d_in[5];
    float* out = (float*)d_out;

    float* qkv_s;
    __half2 *xhi, *whi, *phi, *ahi;
    cudaGetSymbolAddress((void**)&qkv_s, g_qkv);
    cudaGetSymbolAddress((void**)&xhi, g_xhi);
    cudaGetSymbolAddress((void**)&whi, g_whi);
    cudaGetSymbolAddress((void**)&phi, g_phi);
    cudaGetSymbolAddress((void**)&ahi, g_ahi);

    const int M = MTOT;   // 12608

    // 0) pre-split: everything hi-only
    {
        int n4 = M * CDIM / 4;
        split_hi_only<<<(n4 + 255) / 256, 256>>>((const float4*)x, xhi, n4);
        n4 = 3 * CDIM * CDIM / 4;
        split_hi_only<<<(n4 + 255) / 256, 256>>>((const float4*)w_qkv, whi, n4);
        n4 = CDIM * CDIM / 4;
        split_hi_only<<<(n4 + 255) / 256, 256>>>((const float4*)w_proj, phi, n4);
    }

    cudaFuncSetAttribute(gemm_1t, cudaFuncAttributeMaxDynamicSharedMemorySize, GSMEM);

    // 1) QKV GEMM: [M,768] x [2304,768]^T -> [M,2304]
    {
        dim3 grid((3 * CDIM) / 128, (M + 127) / 128);
        gemm_1t<<<grid, 256, GSMEM>>>((const __half*)xhi, (const __half*)whi,
                                      nullptr, qkv_s, M, 3 * CDIM, CDIM);
    }

    // 2) attention (tensorized; hi-only output plane)
    {
        cudaFuncSetAttribute(attn_mma3, cudaFuncAttributeMaxDynamicSharedMemorySize,
                             ATM_SMEM);
        attn_mma3<<<BATCH * NH, 256, ATM_SMEM>>>(qkv_s, rpb, relidx, (uint32_t*)ahi);
    }

    // 3) proj GEMM: [M,768] x [768,768]^T + bias -> out
    {
        dim3 grid(CDIM / 128, (M + 127) / 128);
        gemm_1t<<<grid, 256, GSMEM>>>((const __half*)ahi, (const __half*)phi,
                                      b_proj, out, M, CDIM, CDIM);
    }
}